// round 6
// baseline (speedup 1.0000x reference)
#include <cuda_runtime.h>
#include <cuda_fp16.h>
#include <cuda_pipeline.h>
#include <math.h>

#define Bn   256
#define IC   1152
#define En   8
#define NC   10
#define DV   16
#define JD   160     // NC*DV

// hat kernel tiling
#define HK_ICHUNK 32
#define HK_NCHUNK (IC / HK_ICHUNK)   // 36
#define HK_BTILE  32
#define HK_NBT    (Bn / HK_BTILE)    // 8

// routing kernel
#define RT_THREADS 384
#define RT_WARPS   12
#define CH         96                // i-chunk staged in smem
#define NCHUNKS    (IC / CH)         // 12
#define ROWU4      21                // uint4 per padded smem row (336B = 84 words)
#define U4_PER_BUF (CH * ROWU4)      // 2016
#define SMH_BYTES  (2 * U4_PER_BUF * 16)  // 64512 (double buffered)

// Scratch (static device arrays; no cudaMalloc allowed)
__device__ __half g_hat[(size_t)Bn * IC * JD];            // 94.4 MB (L2-resident)
__device__ float  g_Wt[(size_t)IC * JD * En];             // W transposed: [i][jd][e]
__device__ float  g_c0[(size_t)IC * NC];                  // softmax(bias) per i
__device__ float  g_part0[(size_t)Bn * HK_NCHUNK * JD];   // pass-0 partials

// ---------------------------------------------------------------------------
// Kernel 0: transpose W[i,j,e,d] -> Wt[i, jd, e]; also c0[i,:] = softmax(bias[i,:])
// ---------------------------------------------------------------------------
__global__ __launch_bounds__(128) void transpose_W(
    const float* __restrict__ W, const float* __restrict__ bias)
{
    const int i = blockIdx.x;
    __shared__ float sw[1280 + 80];
    const float* Wi = W + (size_t)i * (NC * En * DV);
#pragma unroll
    for (int o = threadIdx.x; o < NC * En * DV; o += 128)
        sw[o + (o >> 4)] = __ldg(Wi + o);

    // c0: warp 0, lanes 0..9
    if (threadIdx.x < 16) {
        const int l = threadIdx.x;
        float e = (l < NC) ? __expf(__ldg(&bias[i * NC + l])) : 0.f;
        float se = e;
#pragma unroll
        for (int off = 1; off < 16; off <<= 1)
            se += __shfl_xor_sync(0xffffu, se, off);
        if (l < NC) g_c0[i * NC + l] = e * __fdividef(1.f, se);
    }
    __syncthreads();
    float* Wo = g_Wt + (size_t)i * (JD * En);
#pragma unroll
    for (int o = threadIdx.x; o < JD * En; o += 128) {
        const int e = o & 7, jd = o >> 3;
        const int src = (jd >> 4) * (En * DV) + e * DV + (jd & 15);
        Wo[o] = sw[src + (src >> 4)];
    }
}

// ---------------------------------------------------------------------------
// Kernel 1: hat[b,i,jd] = sum_e x[b,i,e]*Wt[i,jd,e] -> fp16 (L2-resident)
// + pass-0 partials with precomputed c0. Lane owns jd slots
// {2l, 2l+1, 64+2l, 65+2l, 128+l}: paired half2 stores + packed converts.
// ---------------------------------------------------------------------------
__global__ __launch_bounds__(256, 2) void hat_s0_kernel(const float* __restrict__ x)
{
    const int chunk = blockIdx.x;
    const int bt    = blockIdx.y;
    const int tid   = threadIdx.x;
    const int w     = tid >> 5;
    const int lane  = tid & 31;
    const int i0    = chunk * HK_ICHUNK;
    const int b0    = bt * HK_BTILE + w * 4;

    const int jds[5] = {2 * lane, 2 * lane + 1, 64 + 2 * lane, 65 + 2 * lane, 128 + lane};

    float acc[4][5];
#pragma unroll
    for (int bb = 0; bb < 4; bb++)
#pragma unroll
        for (int k = 0; k < 5; k++) acc[bb][k] = 0.f;

    for (int il = 0; il < HK_ICHUNK; il++) {
        const int i = i0 + il;

        float wv[5][8];
        const float4* wp = reinterpret_cast<const float4*>(g_Wt + (size_t)i * (JD * En));
#pragma unroll
        for (int k = 0; k < 5; k++) {
            const float4 a = __ldg(wp + jds[k] * 2);
            const float4 c = __ldg(wp + jds[k] * 2 + 1);
            wv[k][0]=a.x; wv[k][1]=a.y; wv[k][2]=a.z; wv[k][3]=a.w;
            wv[k][4]=c.x; wv[k][5]=c.y; wv[k][6]=c.z; wv[k][7]=c.w;
        }

        // precomputed coupling (3 distinct j per lane)
        const float c0a = __ldg(&g_c0[i * NC + (lane >> 3)]);
        const float c0b = __ldg(&g_c0[i * NC + 4 + (lane >> 3)]);
        const float c0c = __ldg(&g_c0[i * NC + 8 + (lane >> 4)]);
        const float c0v[5] = {c0a, c0a, c0b, c0b, c0c};

#pragma unroll
        for (int bb = 0; bb < 4; bb++) {
            const int b = b0 + bb;
            const float4* xp =
                reinterpret_cast<const float4*>(x + ((size_t)b * IC + i) * En);
            const float4 x0 = __ldg(xp);
            const float4 x1 = __ldg(xp + 1);
            const float xv[8] = {x0.x, x0.y, x0.z, x0.w, x1.x, x1.y, x1.z, x1.w};

            float s[5];
#pragma unroll
            for (int k = 0; k < 5; k++) {
                float t = 0.f;
#pragma unroll
                for (int e = 0; e < En; e++) t = fmaf(xv[e], wv[k][e], t);
                s[k] = t;
                acc[bb][k] = fmaf(c0v[k], t, acc[bb][k]);
            }
            __half* hp = g_hat + ((size_t)b * IC + i) * JD;
            *reinterpret_cast<__half2*>(hp + 2 * lane)      = __floats2half2_rn(s[0], s[1]);
            *reinterpret_cast<__half2*>(hp + 64 + 2 * lane) = __floats2half2_rn(s[2], s[3]);
            hp[128 + lane] = __float2half_rn(s[4]);
        }
    }

#pragma unroll
    for (int bb = 0; bb < 4; bb++) {
        float* pp = g_part0 + ((size_t)(b0 + bb) * HK_NCHUNK + chunk) * JD;
#pragma unroll
        for (int k = 0; k < 5; k++) pp[jds[k]] = acc[bb][k];
    }
}

// ---------------------------------------------------------------------------
// Kernel 2: all routing for one b. Double-buffered cp.async (CH=96).
// Phase A: quad-per-i agreement+softmax (conflict-free LDS.128, stride 84w).
// Phase B: lane loads uint4 (8 halves of one j-half), 40-reg fp32 accumulator;
// mapping r=lane&7,g=lane>>3 -> banks 20r+4g+16m all distinct (conflict-free).
// ---------------------------------------------------------------------------
extern __shared__ uint4 smu4[];   // 2 buffers x CH x 21 uint4

__device__ __forceinline__ void load_chunk(int b, int ch, int buf, int tid)
{
    const uint4* src =
        reinterpret_cast<const uint4*>(g_hat + ((size_t)b * IC + ch * CH) * JD);
    uint4* dst = smu4 + buf * U4_PER_BUF;
#pragma unroll
    for (int k = 0; k < 5; k++) {                 // 5*384 = 1920 = CH*20 exactly
        const int q = tid + k * RT_THREADS;
        const int row = q / 20, col = q % 20;
        __pipeline_memcpy_async(dst + row * ROWU4 + col, src + q, 16);
    }
    __pipeline_commit();
}

__global__ __launch_bounds__(RT_THREADS, 2) void route_kernel(
    const float* __restrict__ bias, float* __restrict__ out)
{
    __shared__ float c_f[CH * NC];
    __shared__ float sred[RT_WARPS * JD];
    __shared__ float s_sm[JD], u_f[JD], scale_sm[NC];
    __shared__ __align__(16) __half2 us2[JD / 2];

    const int b    = blockIdx.x;
    const int tid  = threadIdx.x;
    const int w    = tid >> 5;
    const int lane = tid & 31;
    const int quad = tid >> 2;       // Phase A: i within chunk
    const int g4   = tid & 3;
    const int jn   = (g4 < 2) ? 3 : 2;
    const int rB   = lane & 7;       // Phase B row-in-group
    const int gB   = lane >> 3;      // Phase B col group (0..3)

    load_chunk(b, 0, 0, tid);        // prefetch chunk 0 behind v0 compute

    // ---- v0 = squash(sum of pass-0 partials) ----
    if (tid < JD) {
        float s = 0.f;
#pragma unroll
        for (int c = 0; c < HK_NCHUNK; c++)
            s += g_part0[((size_t)b * HK_NCHUNK + c) * JD + tid];
        s_sm[tid] = s;
    }
    __syncthreads();
    if (tid < NC) {
        float s2 = 0.f;
#pragma unroll
        for (int d = 0; d < DV; d++) { float v = s_sm[tid * DV + d]; s2 = fmaf(v, v, s2); }
        scale_sm[tid] = s2 / (1.0f + s2) * rsqrtf(s2);
    }
    __syncthreads();
    if (tid < JD) u_f[tid] = scale_sm[tid >> 4] * s_sm[tid];
    __syncthreads();
    if (tid < JD / 2) us2[tid] = __floats2half2_rn(u_f[2 * tid], u_f[2 * tid + 1]);
    __syncthreads();

    for (int pass = 0; pass < 2; pass++) {
        float acc[5][8];
#pragma unroll
        for (int m = 0; m < 5; m++)
#pragma unroll
            for (int d = 0; d < 8; d++) acc[m][d] = 0.f;

        for (int ch = 0; ch < NCHUNKS; ch++) {
            const int buf = ch & 1;
            if (ch + 1 < NCHUNKS) {
                load_chunk(b, ch + 1, (ch + 1) & 1, tid);
                __pipeline_wait_prior(1);
            } else {
                __pipeline_wait_prior(0);
            }
            __syncthreads();

            // ---- Phase A: quad-per-i agreement + softmax ----
            {
                const uint4* row = smu4 + buf * U4_PER_BUF + quad * ROWU4;
                const int ig = ch * CH + quad;
                float av[3];
                float se = 0.f;
#pragma unroll
                for (int jj = 0; jj < 3; jj++) {
                    if (jj < jn) {
                        const int j = g4 + 4 * jj;
                        const uint4 q0 = row[2 * j];
                        const uint4 q1 = row[2 * j + 1];
                        const __half2* ha = reinterpret_cast<const __half2*>(&q0);
                        const __half2* hb = reinterpret_cast<const __half2*>(&q1);
                        __half2 a2 = __float2half2_rn(0.f);
#pragma unroll
                        for (int m = 0; m < 4; m++) a2 = __hfma2(ha[m], us2[j * 8 + m], a2);
#pragma unroll
                        for (int m = 0; m < 4; m++) a2 = __hfma2(hb[m], us2[j * 8 + 4 + m], a2);
                        av[jj] = __expf(__low2float(a2) + __high2float(a2) +
                                        __ldg(&bias[ig * NC + j]));
                        se += av[jj];
                    }
                }
                se += __shfl_xor_sync(0xffffffffu, se, 1);
                se += __shfl_xor_sync(0xffffffffu, se, 2);
                const float inv = __fdividef(1.f, se);
#pragma unroll
                for (int jj = 0; jj < 3; jj++)
                    if (jj < jn) c_f[quad * NC + g4 + 4 * jj] = av[jj] * inv;
            }
            __syncthreads();

            // ---- Phase B: vectorized weighted sum (uint4 per lane) ----
            {
                const int row = w * 8 + rB;
                const uint4* rowp = smu4 + buf * U4_PER_BUF + row * ROWU4;
                const float* crow = c_f + row * NC;
#pragma unroll
                for (int m = 0; m < 5; m++) {
                    const int col = gB + 4 * m;
                    const uint4 q = rowp[col];
                    const float c = crow[col >> 1];
                    const __half2* h2 = reinterpret_cast<const __half2*>(&q);
#pragma unroll
                    for (int n = 0; n < 4; n++) {
                        const float2 f = __half22float2(h2[n]);
                        acc[m][2 * n]     = fmaf(c, f.x, acc[m][2 * n]);
                        acc[m][2 * n + 1] = fmaf(c, f.y, acc[m][2 * n + 1]);
                    }
                }
            }
            __syncthreads();   // buf consumed
        }

        if (pass == 0) load_chunk(b, 0, 0, tid);   // prefetch pass-1 chunk 0

        // ---- intra-warp reduce over rB (8 lanes, same gB) ----
#pragma unroll
        for (int m = 0; m < 5; m++)
#pragma unroll
            for (int d = 0; d < 8; d++) {
#pragma unroll
                for (int off = 1; off < 8; off <<= 1)
                    acc[m][d] += __shfl_xor_sync(0xffffffffu, acc[m][d], off);
            }
        if (rB == 0) {
#pragma unroll
            for (int m = 0; m < 5; m++) {
                const int jd0 = 8 * (gB + 4 * m);
#pragma unroll
                for (int d = 0; d < 8; d++) sred[w * JD + jd0 + d] = acc[m][d];
            }
        }
        __syncthreads();

        // ---- cross-warp reduce + squash ----
        if (tid < JD) {
            float s = 0.f;
#pragma unroll
            for (int w2 = 0; w2 < RT_WARPS; w2++) s += sred[w2 * JD + tid];
            s_sm[tid] = s;
        }
        __syncthreads();
        if (tid < NC) {
            float s2 = 0.f;
#pragma unroll
            for (int d = 0; d < DV; d++) { float v = s_sm[tid * DV + d]; s2 = fmaf(v, v, s2); }
            scale_sm[tid] = s2 / (1.0f + s2) * rsqrtf(s2);
        }
        __syncthreads();
        if (tid < JD) {
            const float v = scale_sm[tid >> 4] * s_sm[tid];
            if (pass == 0) u_f[tid] += v;                 // u = v0 + v1
            else           out[(size_t)b * JD + tid] = v; // final v2
        }
        __syncthreads();
        if (pass == 0 && tid < JD / 2)
            us2[tid] = __floats2half2_rn(u_f[2 * tid], u_f[2 * tid + 1]);
        __syncthreads();
    }
}

// ---------------------------------------------------------------------------
extern "C" void kernel_launch(void* const* d_in, const int* in_sizes, int n_in,
                              void* d_out, int out_size)
{
    const float* x    = (const float*)d_in[0];
    const float* W    = (const float*)d_in[1];
    const float* bias = (const float*)d_in[2];
    float* out        = (float*)d_out;

    cudaFuncSetAttribute(route_kernel,
                         cudaFuncAttributeMaxDynamicSharedMemorySize, SMH_BYTES);

    transpose_W<<<IC, 128>>>(W, bias);
    hat_s0_kernel<<<dim3(HK_NCHUNK, HK_NBT), 256>>>(x);
    route_kernel<<<Bn, RT_THREADS, SMH_BYTES>>>(bias, out);
}